// round 1
// baseline (speedup 1.0000x reference)
#include <cuda_runtime.h>
#include <math.h>

// Problem constants (fixed by setup_inputs)
#define BB 2
#define SS 2048
#define DD 1024
#define HH 16
#define HD 64
#define MROWS (BB * SS)   // 4096

// Scratch (device globals; no allocation allowed)
__device__ float g_q[MROWS * DD];
__device__ float g_k[MROWS * DD];
__device__ float g_v[MROWS * DD];
__device__ float g_attn[MROWS * DD];
__device__ float g_x[MROWS * DD];

// ---------------------------------------------------------------------------
// SGEMM (NT): C[m,n] = alpha * (sum_k A[m,k] * W[n,k] + bias[n]) (+ res[m,n])
// M=4096, N=1024, K=1024. 128x128 block tile, 256 threads, 8x8 per thread.
// ---------------------------------------------------------------------------
__global__ __launch_bounds__(256) void sgemm_nt(
    const float* __restrict__ A, const float* __restrict__ W,
    const float* __restrict__ bias, const float* __restrict__ res,
    float* __restrict__ C, float alpha)
{
    const int K = DD, N = DD;
    __shared__ float As[8][128];
    __shared__ float Bs[8][128];

    int tid  = threadIdx.x;
    int tx   = tid & 15;       // 0..15
    int ty   = tid >> 4;       // 0..15
    int arow = tid >> 1;       // 0..127
    int acol = (tid & 1) * 4;  // 0 or 4

    const float* Ap = A + (size_t)(blockIdx.y * 128 + arow) * K + acol;
    const float* Bp = W + (size_t)(blockIdx.x * 128 + arow) * K + acol;

    float acc[2][2][4][4];
#pragma unroll
    for (int ri = 0; ri < 2; ++ri)
#pragma unroll
        for (int ci = 0; ci < 2; ++ci)
#pragma unroll
            for (int i = 0; i < 4; ++i)
#pragma unroll
                for (int j = 0; j < 4; ++j)
                    acc[ri][ci][i][j] = 0.f;

    for (int k0 = 0; k0 < K; k0 += 8) {
        float4 av = *(const float4*)(Ap + k0);
        float4 bv = *(const float4*)(Bp + k0);
        As[acol + 0][arow] = av.x;
        As[acol + 1][arow] = av.y;
        As[acol + 2][arow] = av.z;
        As[acol + 3][arow] = av.w;
        Bs[acol + 0][arow] = bv.x;
        Bs[acol + 1][arow] = bv.y;
        Bs[acol + 2][arow] = bv.z;
        Bs[acol + 3][arow] = bv.w;
        __syncthreads();

#pragma unroll
        for (int kk = 0; kk < 8; ++kk) {
            float4 a0 = *(const float4*)&As[kk][ty * 4];
            float4 a1 = *(const float4*)&As[kk][64 + ty * 4];
            float4 b0 = *(const float4*)&Bs[kk][tx * 4];
            float4 b1 = *(const float4*)&Bs[kk][64 + tx * 4];
            float ar[2][4] = {{a0.x, a0.y, a0.z, a0.w}, {a1.x, a1.y, a1.z, a1.w}};
            float br[2][4] = {{b0.x, b0.y, b0.z, b0.w}, {b1.x, b1.y, b1.z, b1.w}};
#pragma unroll
            for (int ri = 0; ri < 2; ++ri)
#pragma unroll
                for (int ci = 0; ci < 2; ++ci)
#pragma unroll
                    for (int i = 0; i < 4; ++i)
#pragma unroll
                        for (int j = 0; j < 4; ++j)
                            acc[ri][ci][i][j] = fmaf(ar[ri][i], br[ci][j], acc[ri][ci][i][j]);
        }
        __syncthreads();
    }

#pragma unroll
    for (int ri = 0; ri < 2; ++ri)
#pragma unroll
        for (int ci = 0; ci < 2; ++ci)
#pragma unroll
            for (int i = 0; i < 4; ++i) {
                int row = blockIdx.y * 128 + ri * 64 + ty * 4 + i;
#pragma unroll
                for (int j = 0; j < 4; ++j) {
                    int col = blockIdx.x * 128 + ci * 64 + tx * 4 + j;
                    float v = (acc[ri][ci][i][j] + bias[col]) * alpha;
                    if (res) v += res[(size_t)row * N + col];
                    C[(size_t)row * N + col] = v;
                }
            }
}

// ---------------------------------------------------------------------------
// Flash attention: per (bh, q-tile of 64). Streams K/V 64-row tiles + the
// extra_attn/mask tiles; online softmax; fp32 throughout.
// 256 threads: thread (ty,tx) in 16x16 grid owns a 4x4 micro-tile.
// ---------------------------------------------------------------------------
#define TSTRIDE 68  // padded smem row stride (floats), multiple of 4

extern __shared__ float smem_attn[];

__global__ __launch_bounds__(256) void attn_kernel(
    const float* __restrict__ extra, const float* __restrict__ mask,
    float* __restrict__ outp)
{
    float* Qs = smem_attn;                 // 64 * TSTRIDE
    float* Ks = Qs + 64 * TSTRIDE;
    float* Vs = Ks + 64 * TSTRIDE;
    float* Ps = Vs + 64 * TSTRIDE;         // also holds E = extra+mask tile

    int tid = threadIdx.x;
    int tx = tid & 15, ty = tid >> 4;
    int bh = blockIdx.y;
    int b = bh >> 4, h = bh & 15;
    int q0 = blockIdx.x * 64;
    const int r0 = ty * 4, c0 = tx * 4;

    // Load Q tile (64 x 64) once
    const float* qbase = g_q + (size_t)(b * SS + q0) * DD + h * HD;
#pragma unroll
    for (int p = 0; p < 4; ++p) {
        int idx = tid + p * 256;
        int row = idx >> 4;
        int c4 = (idx & 15) * 4;
        *(float4*)&Qs[row * TSTRIDE + c4] = *(const float4*)(qbase + (size_t)row * DD + c4);
    }

    float m_i[4], l_i[4], acc[4][4];
#pragma unroll
    for (int i = 0; i < 4; ++i) {
        m_i[i] = -1e30f;
        l_i[i] = 0.f;
#pragma unroll
        for (int j = 0; j < 4; ++j) acc[i][j] = 0.f;
    }

    for (int kt = 0; kt < SS / 64; ++kt) {
        int k0 = kt * 64;
        const float* kbase = g_k + (size_t)(b * SS + k0) * DD + h * HD;
        const float* vbase = g_v + (size_t)(b * SS + k0) * DD + h * HD;
        const float* ebase = extra + (size_t)bh * SS * SS + (size_t)q0 * SS + k0;
        const float* mbase = mask + (size_t)b * SS * SS + (size_t)q0 * SS + k0;

#pragma unroll
        for (int p = 0; p < 4; ++p) {
            int idx = tid + p * 256;
            int row = idx >> 4;
            int c4 = (idx & 15) * 4;
            *(float4*)&Ks[row * TSTRIDE + c4] = *(const float4*)(kbase + (size_t)row * DD + c4);
            *(float4*)&Vs[row * TSTRIDE + c4] = *(const float4*)(vbase + (size_t)row * DD + c4);
            float4 ev = *(const float4*)(ebase + (size_t)row * SS + c4);
            float4 mv = *(const float4*)(mbase + (size_t)row * SS + c4);
            ev.x += mv.x; ev.y += mv.y; ev.z += mv.z; ev.w += mv.w;
            *(float4*)&Ps[row * TSTRIDE + c4] = ev;
        }
        __syncthreads();

        // S = Q @ K^T  (4x4 per thread, k over head_dim=64)
        float sreg[4][4];
#pragma unroll
        for (int i = 0; i < 4; ++i)
#pragma unroll
            for (int j = 0; j < 4; ++j) sreg[i][j] = 0.f;

#pragma unroll 4
        for (int kk = 0; kk < HD; kk += 4) {
            float4 qv[4], kv[4];
#pragma unroll
            for (int i = 0; i < 4; ++i) qv[i] = *(const float4*)&Qs[(r0 + i) * TSTRIDE + kk];
#pragma unroll
            for (int j = 0; j < 4; ++j) kv[j] = *(const float4*)&Ks[(c0 + j) * TSTRIDE + kk];
#pragma unroll
            for (int i = 0; i < 4; ++i)
#pragma unroll
                for (int j = 0; j < 4; ++j) {
                    sreg[i][j] = fmaf(qv[i].x, kv[j].x, sreg[i][j]);
                    sreg[i][j] = fmaf(qv[i].y, kv[j].y, sreg[i][j]);
                    sreg[i][j] = fmaf(qv[i].z, kv[j].z, sreg[i][j]);
                    sreg[i][j] = fmaf(qv[i].w, kv[j].w, sreg[i][j]);
                }
        }

        // add extra + mask (held in Ps)
#pragma unroll
        for (int i = 0; i < 4; ++i)
#pragma unroll
            for (int j = 0; j < 4; ++j)
                sreg[i][j] += Ps[(r0 + i) * TSTRIDE + c0 + j];

        // online softmax (row groups span 16 tx lanes)
#pragma unroll
        for (int i = 0; i < 4; ++i) {
            float mt = fmaxf(fmaxf(sreg[i][0], sreg[i][1]), fmaxf(sreg[i][2], sreg[i][3]));
#pragma unroll
            for (int o = 8; o > 0; o >>= 1)
                mt = fmaxf(mt, __shfl_xor_sync(0xffffffffu, mt, o));
            float mnew = fmaxf(m_i[i], mt);
            float scale = __expf(m_i[i] - mnew);
            float rs = 0.f;
#pragma unroll
            for (int j = 0; j < 4; ++j) {
                float pv = __expf(sreg[i][j] - mnew);
                sreg[i][j] = pv;
                rs += pv;
            }
#pragma unroll
            for (int o = 8; o > 0; o >>= 1)
                rs += __shfl_xor_sync(0xffffffffu, rs, o);
            l_i[i] = l_i[i] * scale + rs;
#pragma unroll
            for (int j = 0; j < 4; ++j) acc[i][j] *= scale;
            m_i[i] = mnew;
        }

        // store P (each thread writes only its own slots, which only it read)
#pragma unroll
        for (int i = 0; i < 4; ++i)
#pragma unroll
            for (int j = 0; j < 4; ++j)
                Ps[(r0 + i) * TSTRIDE + c0 + j] = sreg[i][j];
        __syncthreads();

        // acc += P @ V  (k over 64 keys; V cols = head dims)
#pragma unroll 4
        for (int k = 0; k < 64; ++k) {
            float4 vv = *(const float4*)&Vs[k * TSTRIDE + c0];
#pragma unroll
            for (int i = 0; i < 4; ++i) {
                float pa = Ps[(r0 + i) * TSTRIDE + k];
                acc[i][0] = fmaf(pa, vv.x, acc[i][0]);
                acc[i][1] = fmaf(pa, vv.y, acc[i][1]);
                acc[i][2] = fmaf(pa, vv.z, acc[i][2]);
                acc[i][3] = fmaf(pa, vv.w, acc[i][3]);
            }
        }
        __syncthreads();
    }

    // normalize + write to [B,S,D] layout (un-split heads via indexing)
    float* obase = g_attn + (size_t)(b * SS + q0) * DD + h * HD;
#pragma unroll
    for (int i = 0; i < 4; ++i) {
        float inv = 1.f / l_i[i];
#pragma unroll
        for (int j = 0; j < 4; ++j)
            obase[(size_t)(r0 + i) * DD + c0 + j] = acc[i][j] * inv;
    }
}

// ---------------------------------------------------------------------------
// LayerNorm over last dim (1024), one block (256 thr) per row.
// ---------------------------------------------------------------------------
__global__ __launch_bounds__(256) void ln_kernel(
    const float* __restrict__ x, const float* __restrict__ gamma,
    const float* __restrict__ beta, float* __restrict__ out)
{
    __shared__ float red[8];
    __shared__ float s_mu, s_rs;
    int row = blockIdx.x;
    int tid = threadIdx.x;

    const float4* xr = (const float4*)(x + (size_t)row * DD);
    float4 v = xr[tid];

    float s = v.x + v.y + v.z + v.w;
#pragma unroll
    for (int o = 16; o > 0; o >>= 1) s += __shfl_xor_sync(0xffffffffu, s, o);
    if ((tid & 31) == 0) red[tid >> 5] = s;
    __syncthreads();
    if (tid == 0) {
        float t = 0.f;
#pragma unroll
        for (int w = 0; w < 8; ++w) t += red[w];
        s_mu = t * (1.f / (float)DD);
    }
    __syncthreads();
    float mu = s_mu;

    float d0 = v.x - mu, d1 = v.y - mu, d2 = v.z - mu, d3 = v.w - mu;
    float sq = d0 * d0 + d1 * d1 + d2 * d2 + d3 * d3;
#pragma unroll
    for (int o = 16; o > 0; o >>= 1) sq += __shfl_xor_sync(0xffffffffu, sq, o);
    if ((tid & 31) == 0) red[tid >> 5] = sq;
    __syncthreads();
    if (tid == 0) {
        float t = 0.f;
#pragma unroll
        for (int w = 0; w < 8; ++w) t += red[w];
        s_rs = rsqrtf(t * (1.f / (float)DD) + 1e-5f);
    }
    __syncthreads();
    float rs = s_rs;

    float4 gv = ((const float4*)gamma)[tid];
    float4 bv = ((const float4*)beta)[tid];
    float4 o4;
    o4.x = d0 * rs * gv.x + bv.x;
    o4.y = d1 * rs * gv.y + bv.y;
    o4.z = d2 * rs * gv.z + bv.z;
    o4.w = d3 * rs * gv.w + bv.w;
    ((float4*)(out + (size_t)row * DD))[tid] = o4;
}

// ---------------------------------------------------------------------------
extern "C" void kernel_launch(void* const* d_in, const int* in_sizes, int n_in,
                              void* d_out, int out_size)
{
    const float* hidden = (const float*)d_in[0];
    const float* mask   = (const float*)d_in[1];
    const float* extra  = (const float*)d_in[2];
    const float* Wq = (const float*)d_in[3];
    const float* bq = (const float*)d_in[4];
    const float* Wk = (const float*)d_in[5];
    const float* bk = (const float*)d_in[6];
    const float* Wv = (const float*)d_in[7];
    const float* bv = (const float*)d_in[8];
    const float* Wo = (const float*)d_in[9];
    const float* bo = (const float*)d_in[10];
    const float* gamma = (const float*)d_in[11];
    const float* beta  = (const float*)d_in[12];
    float* out = (float*)d_out;

    float *pq, *pk, *pv, *pattn, *px;
    cudaGetSymbolAddress((void**)&pq, g_q);
    cudaGetSymbolAddress((void**)&pk, g_k);
    cudaGetSymbolAddress((void**)&pv, g_v);
    cudaGetSymbolAddress((void**)&pattn, g_attn);
    cudaGetSymbolAddress((void**)&px, g_x);

    const float scaling = 0.125f;  // head_dim^-0.5, 64^-0.5

    dim3 gproj(DD / 128, MROWS / 128);  // (8, 32)
    sgemm_nt<<<gproj, 256>>>(hidden, Wq, bq, nullptr, pq, scaling);
    sgemm_nt<<<gproj, 256>>>(hidden, Wk, bk, nullptr, pk, 1.0f);
    sgemm_nt<<<gproj, 256>>>(hidden, Wv, bv, nullptr, pv, 1.0f);

    const int smem_attn_bytes = 4 * 64 * TSTRIDE * (int)sizeof(float);  // 69632
    cudaFuncSetAttribute(attn_kernel, cudaFuncAttributeMaxDynamicSharedMemorySize,
                         smem_attn_bytes);
    attn_kernel<<<dim3(SS / 64, BB * HH), 256, smem_attn_bytes>>>(extra, mask, pattn);

    sgemm_nt<<<gproj, 256>>>(pattn, Wo, bo, hidden, px, 1.0f);

    ln_kernel<<<MROWS, 256>>>(px, gamma, beta, out);
}

// round 2
// speedup vs baseline: 2.9859x; 2.9859x over previous
#include <cuda_runtime.h>
#include <math.h>

#define BB 2
#define SS 2048
#define DD 1024
#define HH 16
#define HD 64
#define MROWS (BB * SS)   // 4096

// Scratch (device globals)
__device__ float g_q[MROWS * DD];
__device__ float g_k[MROWS * DD];
__device__ float g_v[MROWS * DD];
__device__ float g_attn[MROWS * DD];
__device__ float g_x[MROWS * DD];

// ---------------------------------------------------------------------------
// tf32 helpers
// ---------------------------------------------------------------------------
__device__ __forceinline__ unsigned f2tf(float f) {
    unsigned r;
    asm("cvt.rna.tf32.f32 %0, %1;" : "=r"(r) : "f"(f));
    return r;
}

// D += A*B, m16n8k8 tf32, fp32 accum
__device__ __forceinline__ void mma_tf32(float* c, const unsigned* a, const unsigned* b) {
    asm volatile(
        "mma.sync.aligned.m16n8k8.row.col.f32.tf32.tf32.f32 "
        "{%0,%1,%2,%3}, {%4,%5,%6,%7}, {%8,%9}, {%0,%1,%2,%3};"
        : "+f"(c[0]), "+f"(c[1]), "+f"(c[2]), "+f"(c[3])
        : "r"(a[0]), "r"(a[1]), "r"(a[2]), "r"(a[3]), "r"(b[0]), "r"(b[1]));
}

// ---------------------------------------------------------------------------
// tf32 GEMM (NT): C[m,n] = alpha*(A@W^T + bias) (+res). M=4096, N=K=1024.
// 128x128 tile, 256 thr (8 warps: 4 along M x 2 along N), warp tile 32x64.
// K-chunk 16.
// ---------------------------------------------------------------------------
#define GST 20  // smem row stride (uints)

__global__ __launch_bounds__(256) void sgemm_tf32(
    const float* __restrict__ A, const float* __restrict__ W,
    const float* __restrict__ bias, const float* __restrict__ res,
    float* __restrict__ C, float alpha)
{
    const int K = DD, N = DD;
    __shared__ unsigned As[128 * GST];
    __shared__ unsigned Bs[128 * GST];

    int tid = threadIdx.x;
    int w = tid >> 5, lane = tid & 31;
    int g = lane >> 2, t = lane & 3;
    int wm = w & 3, wn = w >> 2;

    // G->S mapping: 512 float4 per tile per chunk; 2 per thread
    int r0l = tid >> 2;            // 0..63
    int c4l = (tid & 3) * 4;       // 0,4,8,12

    const float* Ap0 = A + (size_t)(blockIdx.y * 128 + r0l) * K + c4l;
    const float* Ap1 = A + (size_t)(blockIdx.y * 128 + 64 + r0l) * K + c4l;
    const float* Bp0 = W + (size_t)(blockIdx.x * 128 + r0l) * K + c4l;
    const float* Bp1 = W + (size_t)(blockIdx.x * 128 + 64 + r0l) * K + c4l;

    float acc[2][8][4];
#pragma unroll
    for (int i = 0; i < 2; ++i)
#pragma unroll
        for (int j = 0; j < 8; ++j)
#pragma unroll
            for (int q = 0; q < 4; ++q) acc[i][j][q] = 0.f;

    float4 ra0 = *(const float4*)(Ap0);
    float4 ra1 = *(const float4*)(Ap1);
    float4 rb0 = *(const float4*)(Bp0);
    float4 rb1 = *(const float4*)(Bp1);

#pragma unroll 1
    for (int k0 = 0; k0 < K; k0 += 16) {
        // store current chunk
        *(uint4*)&As[r0l * GST + c4l] = make_uint4(f2tf(ra0.x), f2tf(ra0.y), f2tf(ra0.z), f2tf(ra0.w));
        *(uint4*)&As[(64 + r0l) * GST + c4l] = make_uint4(f2tf(ra1.x), f2tf(ra1.y), f2tf(ra1.z), f2tf(ra1.w));
        *(uint4*)&Bs[r0l * GST + c4l] = make_uint4(f2tf(rb0.x), f2tf(rb0.y), f2tf(rb0.z), f2tf(rb0.w));
        *(uint4*)&Bs[(64 + r0l) * GST + c4l] = make_uint4(f2tf(rb1.x), f2tf(rb1.y), f2tf(rb1.z), f2tf(rb1.w));
        __syncthreads();

        if (k0 + 16 < K) {
            ra0 = *(const float4*)(Ap0 + k0 + 16);
            ra1 = *(const float4*)(Ap1 + k0 + 16);
            rb0 = *(const float4*)(Bp0 + k0 + 16);
            rb1 = *(const float4*)(Bp1 + k0 + 16);
        }

#pragma unroll
        for (int k8 = 0; k8 < 2; ++k8) {
            unsigned a[2][4];
#pragma unroll
            for (int i = 0; i < 2; ++i) {
                int r = wm * 32 + i * 16 + g;
                a[i][0] = As[r * GST + k8 * 8 + t];
                a[i][1] = As[(r + 8) * GST + k8 * 8 + t];
                a[i][2] = As[r * GST + k8 * 8 + t + 4];
                a[i][3] = As[(r + 8) * GST + k8 * 8 + t + 4];
            }
#pragma unroll
            for (int j = 0; j < 8; ++j) {
                unsigned b[2];
                int n = wn * 64 + j * 8 + g;
                b[0] = Bs[n * GST + k8 * 8 + t];
                b[1] = Bs[n * GST + k8 * 8 + t + 4];
                mma_tf32(acc[0][j], a[0], b);
                mma_tf32(acc[1][j], a[1], b);
            }
        }
        __syncthreads();
    }

    // epilogue
#pragma unroll
    for (int i = 0; i < 2; ++i) {
        int row_lo = blockIdx.y * 128 + wm * 32 + i * 16 + g;
#pragma unroll
        for (int j = 0; j < 8; ++j) {
            int col = blockIdx.x * 128 + wn * 64 + j * 8 + 2 * t;
            float2 bv = *(const float2*)(bias + col);
            float v0 = (acc[i][j][0] + bv.x) * alpha;
            float v1 = (acc[i][j][1] + bv.y) * alpha;
            float v2 = (acc[i][j][2] + bv.x) * alpha;
            float v3 = (acc[i][j][3] + bv.y) * alpha;
            if (res) {
                float2 r0 = *(const float2*)(res + (size_t)row_lo * N + col);
                float2 r1 = *(const float2*)(res + (size_t)(row_lo + 8) * N + col);
                v0 += r0.x; v1 += r0.y; v2 += r1.x; v3 += r1.y;
            }
            *(float2*)(C + (size_t)row_lo * N + col) = make_float2(v0, v1);
            *(float2*)(C + (size_t)(row_lo + 8) * N + col) = make_float2(v2, v3);
        }
    }
}

// ---------------------------------------------------------------------------
// Flash attention with tf32 mma. Q tile 128, K tile 64, 8 warps (16 rows each).
// ---------------------------------------------------------------------------
#define QT 128
#define KT 64
#define AST 68  // smem stride

__global__ __launch_bounds__(256) void attn_mma(
    const float* __restrict__ gq, const float* __restrict__ gk,
    const float* __restrict__ gv, const float* __restrict__ extra,
    const float* __restrict__ mask, float* __restrict__ gout)
{
    extern __shared__ unsigned sm_u[];
    unsigned* Qs = sm_u;                  // 128*AST
    unsigned* Ks = Qs + QT * AST;         // 64*AST
    unsigned* Vt = Ks + KT * AST;         // 64*AST (transposed: [hd][key])
    unsigned* Ps = Vt + KT * AST;         // 128*AST

    int tid = threadIdx.x;
    int w = tid >> 5, lane = tid & 31;
    int g = lane >> 2, t = lane & 3;
    int bh = blockIdx.y, b = bh >> 4, h = bh & 15;
    int q0 = blockIdx.x * QT;

    // load Q tile (128 x 64)
    const float* qb = gq + (size_t)(b * SS + q0) * DD + h * HD;
#pragma unroll
    for (int p = 0; p < 8; ++p) {
        int idx = tid + p * 256;
        int row = idx >> 4;
        int c4 = (idx & 15) * 4;
        float4 v = *(const float4*)(qb + (size_t)row * DD + c4);
        *(uint4*)&Qs[row * AST + c4] = make_uint4(f2tf(v.x), f2tf(v.y), f2tf(v.z), f2tf(v.w));
    }

    float o[8][4];
    float m_[2], l_[2];
#pragma unroll
    for (int j = 0; j < 8; ++j)
#pragma unroll
        for (int q = 0; q < 4; ++q) o[j][q] = 0.f;
    m_[0] = m_[1] = -1e30f;
    l_[0] = l_[1] = 0.f;

    int r_lo = w * 16 + g;
    int r_hi = r_lo + 8;
    const float* ebase = extra + (size_t)bh * SS * SS + (size_t)q0 * SS;
    const float* mbase = mask + (size_t)b * SS * SS + (size_t)q0 * SS;

#pragma unroll 1
    for (int kt = 0; kt < SS / KT; ++kt) {
        int k0 = kt * KT;
        const float* kb = gk + (size_t)(b * SS + k0) * DD + h * HD;
        const float* vb = gv + (size_t)(b * SS + k0) * DD + h * HD;

        __syncthreads();  // prev iter's Ks/Vt/Ps reads complete
#pragma unroll
        for (int p = 0; p < 4; ++p) {
            int idx = tid + p * 256;
            int row = idx >> 4;         // 0..63 key
            int c4 = (idx & 15) * 4;    // hd
            float4 kv = *(const float4*)(kb + (size_t)row * DD + c4);
            *(uint4*)&Ks[row * AST + c4] = make_uint4(f2tf(kv.x), f2tf(kv.y), f2tf(kv.z), f2tf(kv.w));
            float4 vv = *(const float4*)(vb + (size_t)row * DD + c4);
            Vt[(c4 + 0) * AST + row] = f2tf(vv.x);
            Vt[(c4 + 1) * AST + row] = f2tf(vv.y);
            Vt[(c4 + 2) * AST + row] = f2tf(vv.z);
            Vt[(c4 + 3) * AST + row] = f2tf(vv.w);
        }
        __syncthreads();

        // S = Q @ K^T : 16x64 per warp
        float s[8][4];
#pragma unroll
        for (int j = 0; j < 8; ++j)
#pragma unroll
            for (int q = 0; q < 4; ++q) s[j][q] = 0.f;

#pragma unroll
        for (int k8 = 0; k8 < 8; ++k8) {
            unsigned a[4];
            a[0] = Qs[r_lo * AST + k8 * 8 + t];
            a[1] = Qs[r_hi * AST + k8 * 8 + t];
            a[2] = Qs[r_lo * AST + k8 * 8 + t + 4];
            a[3] = Qs[r_hi * AST + k8 * 8 + t + 4];
#pragma unroll
            for (int j = 0; j < 8; ++j) {
                unsigned bb[2];
                bb[0] = Ks[(j * 8 + g) * AST + k8 * 8 + t];
                bb[1] = Ks[(j * 8 + g) * AST + k8 * 8 + t + 4];
                mma_tf32(s[j], a, bb);
            }
        }

        // add extra + mask
#pragma unroll
        for (int j = 0; j < 8; ++j) {
            int c = k0 + j * 8 + 2 * t;
            float2 e0 = *(const float2*)(ebase + (size_t)r_lo * SS + c);
            float2 e1 = *(const float2*)(ebase + (size_t)r_hi * SS + c);
            float2 a0 = *(const float2*)(mbase + (size_t)r_lo * SS + c);
            float2 a1 = *(const float2*)(mbase + (size_t)r_hi * SS + c);
            s[j][0] += e0.x + a0.x;
            s[j][1] += e0.y + a0.y;
            s[j][2] += e1.x + a1.x;
            s[j][3] += e1.y + a1.y;
        }

        // online softmax (rows r_lo, r_hi; reduce over quad lanes)
        float mx0 = -1e30f, mx1 = -1e30f;
#pragma unroll
        for (int j = 0; j < 8; ++j) {
            mx0 = fmaxf(mx0, fmaxf(s[j][0], s[j][1]));
            mx1 = fmaxf(mx1, fmaxf(s[j][2], s[j][3]));
        }
        mx0 = fmaxf(mx0, __shfl_xor_sync(0xffffffffu, mx0, 1));
        mx0 = fmaxf(mx0, __shfl_xor_sync(0xffffffffu, mx0, 2));
        mx1 = fmaxf(mx1, __shfl_xor_sync(0xffffffffu, mx1, 1));
        mx1 = fmaxf(mx1, __shfl_xor_sync(0xffffffffu, mx1, 2));

        float mn0 = fmaxf(m_[0], mx0);
        float mn1 = fmaxf(m_[1], mx1);
        float sc0 = __expf(m_[0] - mn0);
        float sc1 = __expf(m_[1] - mn1);
        float sum0 = 0.f, sum1 = 0.f;
#pragma unroll
        for (int j = 0; j < 8; ++j) {
            s[j][0] = __expf(s[j][0] - mn0);
            s[j][1] = __expf(s[j][1] - mn0);
            s[j][2] = __expf(s[j][2] - mn1);
            s[j][3] = __expf(s[j][3] - mn1);
            sum0 += s[j][0] + s[j][1];
            sum1 += s[j][2] + s[j][3];
        }
        sum0 += __shfl_xor_sync(0xffffffffu, sum0, 1);
        sum0 += __shfl_xor_sync(0xffffffffu, sum0, 2);
        sum1 += __shfl_xor_sync(0xffffffffu, sum1, 1);
        sum1 += __shfl_xor_sync(0xffffffffu, sum1, 2);
        l_[0] = l_[0] * sc0 + sum0;
        l_[1] = l_[1] * sc1 + sum1;
        m_[0] = mn0;
        m_[1] = mn1;
#pragma unroll
        for (int j = 0; j < 8; ++j) {
            o[j][0] *= sc0; o[j][1] *= sc0;
            o[j][2] *= sc1; o[j][3] *= sc1;
        }

        // store P (tf32)
#pragma unroll
        for (int j = 0; j < 8; ++j) {
            *(uint2*)&Ps[r_lo * AST + j * 8 + 2 * t] = make_uint2(f2tf(s[j][0]), f2tf(s[j][1]));
            *(uint2*)&Ps[r_hi * AST + j * 8 + 2 * t] = make_uint2(f2tf(s[j][2]), f2tf(s[j][3]));
        }
        __syncthreads();

        // O += P @ V : A = P[16 x 64keys], B = Vt
#pragma unroll
        for (int k8 = 0; k8 < 8; ++k8) {
            unsigned a[4];
            a[0] = Ps[r_lo * AST + k8 * 8 + t];
            a[1] = Ps[r_hi * AST + k8 * 8 + t];
            a[2] = Ps[r_lo * AST + k8 * 8 + t + 4];
            a[3] = Ps[r_hi * AST + k8 * 8 + t + 4];
#pragma unroll
            for (int j = 0; j < 8; ++j) {
                unsigned bb[2];
                bb[0] = Vt[(j * 8 + g) * AST + k8 * 8 + t];
                bb[1] = Vt[(j * 8 + g) * AST + k8 * 8 + t + 4];
                mma_tf32(o[j], a, bb);
            }
        }
    }

    // epilogue
    float inv0 = 1.f / l_[0];
    float inv1 = 1.f / l_[1];
    float* ob = gout + (size_t)(b * SS + q0) * DD + h * HD;
#pragma unroll
    for (int j = 0; j < 8; ++j) {
        int c = j * 8 + 2 * t;
        *(float2*)(ob + (size_t)r_lo * DD + c) = make_float2(o[j][0] * inv0, o[j][1] * inv0);
        *(float2*)(ob + (size_t)r_hi * DD + c) = make_float2(o[j][2] * inv1, o[j][3] * inv1);
    }
}

// ---------------------------------------------------------------------------
// LayerNorm over last dim (1024), one block (256 thr) per row.
// ---------------------------------------------------------------------------
__global__ __launch_bounds__(256) void ln_kernel(
    const float* __restrict__ x, const float* __restrict__ gamma,
    const float* __restrict__ beta, float* __restrict__ out)
{
    __shared__ float red[8];
    __shared__ float s_mu, s_rs;
    int row = blockIdx.x;
    int tid = threadIdx.x;

    const float4* xr = (const float4*)(x + (size_t)row * DD);
    float4 v = xr[tid];

    float s = v.x + v.y + v.z + v.w;
#pragma unroll
    for (int o = 16; o > 0; o >>= 1) s += __shfl_xor_sync(0xffffffffu, s, o);
    if ((tid & 31) == 0) red[tid >> 5] = s;
    __syncthreads();
    if (tid == 0) {
        float tt = 0.f;
#pragma unroll
        for (int q = 0; q < 8; ++q) tt += red[q];
        s_mu = tt * (1.f / (float)DD);
    }
    __syncthreads();
    float mu = s_mu;

    float d0 = v.x - mu, d1 = v.y - mu, d2 = v.z - mu, d3 = v.w - mu;
    float sq = d0 * d0 + d1 * d1 + d2 * d2 + d3 * d3;
#pragma unroll
    for (int o = 16; o > 0; o >>= 1) sq += __shfl_xor_sync(0xffffffffu, sq, o);
    if ((tid & 31) == 0) red[tid >> 5] = sq;
    __syncthreads();
    if (tid == 0) {
        float tt = 0.f;
#pragma unroll
        for (int q = 0; q < 8; ++q) tt += red[q];
        s_rs = rsqrtf(tt * (1.f / (float)DD) + 1e-5f);
    }
    __syncthreads();
    float rs = s_rs;

    float4 gv = ((const float4*)gamma)[tid];
    float4 bv = ((const float4*)beta)[tid];
    float4 o4;
    o4.x = d0 * rs * gv.x + bv.x;
    o4.y = d1 * rs * gv.y + bv.y;
    o4.z = d2 * rs * gv.z + bv.z;
    o4.w = d3 * rs * gv.w + bv.w;
    ((float4*)(out + (size_t)row * DD))[tid] = o4;
}

// ---------------------------------------------------------------------------
extern "C" void kernel_launch(void* const* d_in, const int* in_sizes, int n_in,
                              void* d_out, int out_size)
{
    const float* hidden = (const float*)d_in[0];
    const float* mask   = (const float*)d_in[1];
    const float* extra  = (const float*)d_in[2];
    const float* Wq = (const float*)d_in[3];
    const float* bq = (const float*)d_in[4];
    const float* Wk = (const float*)d_in[5];
    const float* bk = (const float*)d_in[6];
    const float* Wv = (const float*)d_in[7];
    const float* bv = (const float*)d_in[8];
    const float* Wo = (const float*)d_in[9];
    const float* bo = (const float*)d_in[10];
    const float* gamma = (const float*)d_in[11];
    const float* beta  = (const float*)d_in[12];
    float* out = (float*)d_out;

    float *pq, *pk, *pv, *pattn, *px;
    cudaGetSymbolAddress((void**)&pq, g_q);
    cudaGetSymbolAddress((void**)&pk, g_k);
    cudaGetSymbolAddress((void**)&pv, g_v);
    cudaGetSymbolAddress((void**)&pattn, g_attn);
    cudaGetSymbolAddress((void**)&px, g_x);

    const float scaling = 0.125f;  // 64^-0.5

    dim3 gproj(DD / 128, MROWS / 128);  // (8, 32)
    sgemm_tf32<<<gproj, 256>>>(hidden, Wq, bq, nullptr, pq, scaling);
    sgemm_tf32<<<gproj, 256>>>(hidden, Wk, bk, nullptr, pk, 1.0f);
    sgemm_tf32<<<gproj, 256>>>(hidden, Wv, bv, nullptr, pv, 1.0f);

    const int smem_attn = (QT * AST + KT * AST + KT * AST + QT * AST) * 4;  // 104448
    cudaFuncSetAttribute(attn_mma, cudaFuncAttributeMaxDynamicSharedMemorySize, smem_attn);
    attn_mma<<<dim3(SS / QT, BB * HH), 256, smem_attn>>>(pq, pk, pv, extra, mask, pattn);

    sgemm_tf32<<<gproj, 256>>>(pattn, Wo, bo, hidden, px, 1.0f);

    ln_kernel<<<MROWS, 256>>>(px, gamma, beta, out);
}